// round 15
// baseline (speedup 1.0000x reference)
#include <cuda_runtime.h>
#include <cuda_bf16.h>
#include <stdint.h>
#include <math.h>

#define B      512
#define H      512
#define TENC   512
#define TDEC   128
#define TTOT   640
#define NMT    4
#define NTHREADS 512

#define ASTAGE_BYTES 32768   // hh 16KB + hl 16KB per pair-stage
#define NASTAGE 3
#define WOFF   (NASTAGE * ASTAGE_BYTES)        // 98304
#define SMEM_DYN (WOFF + 16 * 8192 + 1024)     // 230400 <= 232448

// ---------------- persistent device state (no allocation allowed) ----------
static __device__ __align__(16) __nv_bfloat16 g_hhi0[B * H];
static __device__ __align__(16) __nv_bfloat16 g_hhi1[B * H];
static __device__ __align__(16) __nv_bfloat16 g_hlo0[B * H];
static __device__ __align__(16) __nv_bfloat16 g_hlo1[B * H];
static __device__ float g_xpart[32 * B];               // [nt][b] partial lin(h)
static __device__ __align__(16) __nv_bfloat16 g_whi_e[2048 * 512];
static __device__ __align__(16) __nv_bfloat16 g_wlo_e[2048 * 512];
static __device__ __align__(16) __nv_bfloat16 g_whi_d[2048 * 512];
static __device__ __align__(16) __nv_bfloat16 g_wlo_d[2048 * 512];
static __device__ __align__(16) unsigned g_step[NMT * 32];   // steps completed per CTA

// ---------------- helpers ----------------------------------------------------
__device__ __forceinline__ uint32_t smem_u32(const void* p) {
    uint32_t a;
    asm("{ .reg .u64 t; cvta.to.shared.u64 t, %1; cvt.u32.u64 %0, t; }"
        : "=r"(a) : "l"(p));
    return a;
}
__device__ __forceinline__ void cp16(uint32_t dst, const void* src) {
    asm volatile("cp.async.cg.shared.global [%0], [%1], 16;" :: "r"(dst), "l"(src));
}
__device__ __forceinline__ void cp_commit() {
    asm volatile("cp.async.commit_group;" ::: "memory");
}
__device__ __forceinline__ void cp_wait1() {
    asm volatile("cp.async.wait_group 1;" ::: "memory");
}
__device__ __forceinline__ void cp_wait0() {
    asm volatile("cp.async.wait_group 0;" ::: "memory");
}
__device__ __forceinline__ void ldsm_x4(uint32_t& r0, uint32_t& r1,
                                        uint32_t& r2, uint32_t& r3, uint32_t addr) {
    asm volatile("ldmatrix.sync.aligned.m8n8.x4.shared.b16 {%0,%1,%2,%3}, [%4];"
                 : "=r"(r0), "=r"(r1), "=r"(r2), "=r"(r3) : "r"(addr));
}
__device__ __forceinline__ void mma_bf16(float* c, const uint32_t* a,
                                         uint32_t b0, uint32_t b1) {
    asm volatile(
        "mma.sync.aligned.m16n8k16.row.col.f32.bf16.bf16.f32 "
        "{%0,%1,%2,%3}, {%4,%5,%6,%7}, {%8,%9}, {%0,%1,%2,%3};"
        : "+f"(c[0]), "+f"(c[1]), "+f"(c[2]), "+f"(c[3])
        : "r"(a[0]), "r"(a[1]), "r"(a[2]), "r"(a[3]), "r"(b0), "r"(b1));
}
__device__ __forceinline__ float sigf(float x) { return 1.0f / (1.0f + __expf(-x)); }
__device__ __forceinline__ float tanhe(float x) {
    return __fmaf_rn(2.0f, sigf(2.0f * x), -1.0f);
}
__device__ __forceinline__ uint4 ld_acq4(const unsigned* p) {
    uint4 v;
    asm volatile("ld.global.acquire.gpu.v4.u32 {%0,%1,%2,%3}, [%4];"
                 : "=r"(v.x), "=r"(v.y), "=r"(v.z), "=r"(v.w) : "l"(p) : "memory");
    return v;
}
__device__ __forceinline__ void st_rel(unsigned* p, unsigned v) {
    asm volatile("st.global.release.gpu.u32 [%0], %1;" :: "l"(p), "r"(v) : "memory");
}

// ---------------- prologue kernels -------------------------------------------
// Repack W (2048,512): packed row n' = nt*64 + g*16 + jl  <->  n = g*512 + nt*16 + jl
__global__ void pack_w_kernel(const float* __restrict__ W,
                              __nv_bfloat16* __restrict__ whi,
                              __nv_bfloat16* __restrict__ wlo) {
    int idx = blockIdx.x * 256 + threadIdx.x;
    int np = idx >> 9, k = idx & 511;
    int nt = np >> 6, r = np & 63;
    int n = (r >> 4) * 512 + nt * 16 + (r & 15);
    float w = W[n * 512 + k];
    __nv_bfloat16 hi = __float2bfloat16_rn(w);
    whi[idx] = hi;
    wlo[idx] = __float2bfloat16_rn(w - __bfloat162float(hi));
}

__global__ void zero_state_kernel() {
    int i = blockIdx.x * 256 + threadIdx.x;
    if (i < B * H) {
        g_hhi0[i] = __float2bfloat16(0.0f);
        g_hlo0[i] = __float2bfloat16(0.0f);
    }
    if (i < NMT * 32) g_step[i] = 0u;   // graph-replay-safe reset
}

// ---------------- the persistent encoder-decoder kernel ----------------------
__global__ void __launch_bounds__(NTHREADS, 1)
lstm_persistent(const float* __restrict__ inputs,
                const __nv_bfloat16* __restrict__ whiE, const __nv_bfloat16* __restrict__ wloE,
                const __nv_bfloat16* __restrict__ whiD, const __nv_bfloat16* __restrict__ wloD,
                const float* __restrict__ encWih, const float* __restrict__ encB,
                const float* __restrict__ decWih, const float* __restrict__ decB,
                const float* __restrict__ linW, const float* __restrict__ linb,
                float* __restrict__ out)
{
    extern __shared__ char dsmem[];
    uint32_t raw = smem_u32(dsmem);
    uint32_t sb  = (raw + 1023) & ~1023u;
    char* sp     = dsmem + (sb - raw);
    float* zs    = (float*)sp;     // 128 x 68 f32 (34 KB), reuses A stages post-drain

    const int tid  = threadIdx.x;
    const int wid  = tid >> 5;
    const int lane = tid & 31;
    const int wm   = wid >> 2;     // 0..3 : 32-row warp tile
    const int wn   = wid & 3;      // 0..3 : 16-col warp tile
    const int nt   = blockIdx.x;   // 0..31
    const int mt   = blockIdx.y;   // 0..3
    const int brow0 = mt * 128;

    unsigned* flags = g_step + mt * 32;

    // ---- staging map: thread covers 16B in 2 rows of a 128x64 chunk ---------
    const int gr  = tid >> 3;             // 0..63
    const int gce = (tid & 7) * 8;        // element col
    uint32_t soA[2];
#pragma unroll
    for (int i = 0; i < 2; i++) {
        int row = gr + 64 * i;
        soA[i] = (uint32_t)row * 128u + (((uint32_t)gce * 2) ^ (uint32_t)((row & 7) << 4));
    }

    // ---- ldmatrix addressing --------------------------------------------------
    const int lrow = lane & 15;
    const uint32_t kb2 = (uint32_t)((lane >> 4) * 16);
    uint32_t aoff[2], axor[2], boff, bxor;
#pragma unroll
    for (int mi = 0; mi < 2; mi++) {
        int r = wm * 32 + mi * 16 + lrow;
        aoff[mi] = (uint32_t)r * 128u;
        axor[mi] = (uint32_t)((r & 7) << 4);
    }
    {
        int r = wn * 16 + lrow;
        boff = (uint32_t)r * 128u;
        bxor = (uint32_t)((r & 7) << 4);
    }

    // ---- load W tiles into smem (16 tiles x 8KB: Wh kc0..7, Wl kc0..7) ------
    auto load_w = [&](const __nv_bfloat16* wh, const __nv_bfloat16* wl) {
#pragma unroll 4
        for (int j = 0; j < 16; ++j) {
            int slot = tid + j * NTHREADS;
            int tile = slot >> 9;
            int win  = slot & 511;
            int row  = win >> 3;
            int ce   = (win & 7) * 8;
            const __nv_bfloat16* src = ((tile >> 3) ? wl : wh)
                + (size_t)(nt * 64 + row) * 512 + (tile & 7) * 64 + ce;
            uint32_t dst = sb + WOFF + (uint32_t)tile * 8192u
                + (uint32_t)row * 128u
                + (((uint32_t)ce * 2u) ^ (uint32_t)((row & 7) << 4));
            cp16(dst, src);
        }
        cp_commit();
        cp_wait0();
        __syncthreads();
    };

    load_w(whiE, wloE);
    const float* Wih  = encWih;
    const float* bias = encB;

    // ---- epilogue constants ----------------------------------------------------
    const int q    = tid & 3;
    const int eml  = tid >> 2;            // 0..127 (batch row in tile)
    const int jl0  = q * 4;
    const int jh0  = nt * 16 + jl0;
    const float lbv = __ldg(linb);
    const float4 lw = __ldg((const float4*)(linW + jh0));

    float creg[4];                        // cell state lives in registers
#pragma unroll
    for (int j = 0; j < 4; j++) creg[j] = 0.0f;

    // wait for the 4 producer CTAs of chunk p to have completed >= want steps
    auto wait_chunk = [&](int p, unsigned want) {
        const unsigned* fp = flags + 4 * p;
        uint4 v = ld_acq4(fp);
        while (v.x < want || v.y < want || v.z < want || v.w < want) {
            __nanosleep(32);
            v = ld_acq4(fp);
        }
    };

    for (int t = 0; t < TTOT; ++t) {
        if (t == TENC) {
            load_w(whiD, wloD);
            Wih = decWih; bias = decB;
        }
        const __nv_bfloat16* hi = (t & 1) ? g_hhi1 : g_hhi0;
        const __nv_bfloat16* lo = (t & 1) ? g_hlo1 : g_hlo0;
        __nv_bfloat16* hio = (t & 1) ? g_hhi0 : g_hhi1;
        __nv_bfloat16* loo = (t & 1) ? g_hlo0 : g_hlo1;
        const unsigned want = (unsigned)t;

        float acc[2][2][4];
#pragma unroll
        for (int mi = 0; mi < 2; mi++)
#pragma unroll
            for (int ni = 0; ni < 2; ni++)
#pragma unroll
                for (int qq = 0; qq < 4; qq++) acc[mi][ni][qq] = 0.0f;

        auto issue_pair = [&](int p) {
            wait_chunk(p, want);
            const uint32_t ab = sb + (uint32_t)(p % 3) * ASTAGE_BYTES;
#pragma unroll
            for (int i = 0; i < 2; ++i) {
                const int row = gr + 64 * i;
                const size_t go = (size_t)(brow0 + row) * 512 + p * 64 + gce;
                cp16(ab + soA[i],          hi + go);
                cp16(ab + 16384u + soA[i], lo + go);
            }
            cp_commit();
        };

        auto compute_pair = [&](int p) {
            const uint32_t ab  = sb + (uint32_t)(p % 3) * ASTAGE_BYTES;
            const uint32_t alb = ab + 16384u;
            const uint32_t whb = sb + WOFF + (uint32_t)p * 8192u;
            const uint32_t wlb = whb + 65536u;
#pragma unroll
            for (int s = 0; s < 4; ++s) {
                const uint32_t kb = (uint32_t)(s * 32);
                uint32_t ah[2][4], al[2][4];
#pragma unroll
                for (int mi = 0; mi < 2; ++mi) {
                    const uint32_t off = aoff[mi] + ((kb + kb2) ^ axor[mi]);
                    ldsm_x4(ah[mi][0], ah[mi][1], ah[mi][2], ah[mi][3], ab  + off);
                    ldsm_x4(al[mi][0], al[mi][1], al[mi][2], al[mi][3], alb + off);
                }
                uint32_t bh[2][2], bl[2][2];
                {
                    const uint32_t off = boff + ((kb + kb2) ^ bxor);
                    uint32_t q0, q1, q2, q3;
                    ldsm_x4(q0, q1, q2, q3, whb + off);
                    bh[0][0] = q0; bh[0][1] = q2;
                    bh[1][0] = q1; bh[1][1] = q3;
                    ldsm_x4(q0, q1, q2, q3, wlb + off);
                    bl[0][0] = q0; bl[0][1] = q2;
                    bl[1][0] = q1; bl[1][1] = q3;
                }
#pragma unroll
                for (int mi = 0; mi < 2; ++mi)
#pragma unroll
                    for (int ni = 0; ni < 2; ++ni) {
                        mma_bf16(acc[mi][ni], ah[mi], bh[ni][0], bh[ni][1]);
                        mma_bf16(acc[mi][ni], ah[mi], bl[ni][0], bl[ni][1]);
                        mma_bf16(acc[mi][ni], al[mi], bh[ni][0], bh[ni][1]);
                    }
            }
        };

        // pipeline: 8 pairs, 3 stages, per-chunk producer flags
        issue_pair(0);
        issue_pair(1);
        for (int p = 0; p < 8; ++p) {
            cp_wait1();
            __syncthreads();
            if (p + 2 < 8) issue_pair(p + 2);
            else           cp_commit();       // keep group count advancing
            compute_pair(p);
        }
        cp_wait0();
        __syncthreads();   // all compute done before zs overwrites stages 0-1

        // ---- accum -> zs (stride 68) -----------------------------------------
        {
            const int g  = lane >> 2;
            const int t2 = (lane & 3) * 2;
#pragma unroll
            for (int mi = 0; mi < 2; mi++)
#pragma unroll
                for (int ni = 0; ni < 2; ni++) {
                    const int row = wm * 32 + mi * 16 + g;
                    const int col = wn * 16 + ni * 8 + t2;
                    *(float2*)(zs + row * 68 + col) =
                        make_float2(acc[mi][ni][0], acc[mi][ni][1]);
                    *(float2*)(zs + (row + 8) * 68 + col) =
                        make_float2(acc[mi][ni][2], acc[mi][ni][3]);
                }
        }
        __syncthreads();

        // ---- gate pass: one row x 4 jh per thread -------------------------------
        {
            const int r = eml;
            const int b = brow0 + r;

            float xv;
            if (t < TENC) {
                xv = __ldg(inputs + (size_t)b * 512 + t);
            } else if (t == TENC) {
                xv = __ldg(inputs + (size_t)b * 512 + 511);
            } else {
                float s = 0.0f;
#pragma unroll
                for (int i = 0; i < 8; ++i)
                    s += g_xpart[(q * 8 + i) * B + b];
                s += __shfl_xor_sync(0xffffffffu, s, 1);
                s += __shfl_xor_sync(0xffffffffu, s, 2);
                xv = s + lbv;
                if (nt == 0 && q == 0)
                    out[(size_t)b * TDEC + (t - TENC - 1)] = xv;
            }

            const float4 wi0 = __ldg((const float4*)(Wih + jh0));
            const float4 wi1 = __ldg((const float4*)(Wih + 512 + jh0));
            const float4 wi2 = __ldg((const float4*)(Wih + 1024 + jh0));
            const float4 wi3 = __ldg((const float4*)(Wih + 1536 + jh0));
            const float4 bq0 = __ldg((const float4*)(bias + jh0));
            const float4 bq1 = __ldg((const float4*)(bias + 512 + jh0));
            const float4 bq2 = __ldg((const float4*)(bias + 1024 + jh0));
            const float4 bq3 = __ldg((const float4*)(bias + 1536 + jh0));

            float zi[4], zf[4], zg[4], zo[4];
            *(float4*)zi = *(const float4*)(zs + r * 68 +      jl0);
            *(float4*)zf = *(const float4*)(zs + r * 68 + 16 + jl0);
            *(float4*)zg = *(const float4*)(zs + r * 68 + 32 + jl0);
            *(float4*)zo = *(const float4*)(zs + r * 68 + 48 + jl0);

            const float* w0 = (const float*)&wi0; const float* b0p = (const float*)&bq0;
            const float* w1 = (const float*)&wi1; const float* b1p = (const float*)&bq1;
            const float* w2 = (const float*)&wi2; const float* b2p = (const float*)&bq2;
            const float* w3 = (const float*)&wi3; const float* b3p = (const float*)&bq3;

            float hv[4];
#pragma unroll
            for (int j = 0; j < 4; ++j) {
                const float vi = zi[j] + xv * w0[j] + b0p[j];
                const float vf = zf[j] + xv * w1[j] + b1p[j];
                const float vg = zg[j] + xv * w2[j] + b2p[j];
                const float vo = zo[j] + xv * w3[j] + b3p[j];
                const float cn = sigf(vf) * creg[j] + sigf(vi) * tanhe(vg);
                creg[j] = cn;
                hv[j] = sigf(vo) * tanhe(cn);
            }

            __nv_bfloat162 hh01 = __floats2bfloat162_rn(hv[0], hv[1]);
            __nv_bfloat162 hh23 = __floats2bfloat162_rn(hv[2], hv[3]);
            float l0 = hv[0] - __bfloat162float(__low2bfloat16(hh01));
            float l1 = hv[1] - __bfloat162float(__high2bfloat16(hh01));
            float l2 = hv[2] - __bfloat162float(__low2bfloat16(hh23));
            float l3 = hv[3] - __bfloat162float(__high2bfloat16(hh23));
            __nv_bfloat162 hl01 = __floats2bfloat162_rn(l0, l1);
            __nv_bfloat162 hl23 = __floats2bfloat162_rn(l2, l3);
            uint2 hp, lp;
            hp.x = *(uint32_t*)&hh01; hp.y = *(uint32_t*)&hh23;
            lp.x = *(uint32_t*)&hl01; lp.y = *(uint32_t*)&hl23;
            const size_t oidx = (size_t)b * H + jh0;
            *(uint2*)(hio + oidx) = hp;
            *(uint2*)(loo + oidx) = lp;

            if (t >= TENC) {   // partial lin(h_t) for the next step's x
                float s = hv[0] * lw.x + hv[1] * lw.y + hv[2] * lw.z + hv[3] * lw.w;
                s += __shfl_xor_sync(0xffffffffu, s, 1);
                s += __shfl_xor_sync(0xffffffffu, s, 2);
                if (q == 0) g_xpart[nt * B + b] = s;
            }
        }

        // ---- publish: this CTA finished step t ----------------------------------
        __threadfence();
        __syncthreads();
        if (tid == 0) st_rel(&flags[nt], (unsigned)(t + 1));
    }

    // ---- final output column: out[:, 127] = lin(h_final) -----------------------
    if (nt == 0) {
        for (int p = 0; p < 8; ++p) wait_chunk(p, (unsigned)TTOT);
        if (tid < 128) {
            const int b = brow0 + tid;
            float s = lbv;
#pragma unroll
            for (int i = 0; i < 32; ++i) s += g_xpart[i * B + b];
            out[(size_t)b * TDEC + (TDEC - 1)] = s;
        }
    }
}

// ---------------- launch ------------------------------------------------------
extern "C" void kernel_launch(void* const* d_in, const int* in_sizes, int n_in,
                              void* d_out, int out_size)
{
    (void)in_sizes; (void)n_in; (void)out_size;
    const float* inputs = (const float*)d_in[0];
    // d_in[1] = targets (unused: teacher_forcing_ratio == 0)
    const float* encWih = (const float*)d_in[2];
    const float* encWhh = (const float*)d_in[3];
    const float* encB   = (const float*)d_in[4];
    const float* decWih = (const float*)d_in[5];
    const float* decWhh = (const float*)d_in[6];
    const float* decB   = (const float*)d_in[7];
    const float* linW   = (const float*)d_in[8];
    const float* linB   = (const float*)d_in[9];
    float* out = (float*)d_out;

    cudaFuncSetAttribute(lstm_persistent,
                         cudaFuncAttributeMaxDynamicSharedMemorySize, SMEM_DYN);

    __nv_bfloat16 *whiE, *wloE, *whiD, *wloD;
    cudaGetSymbolAddress((void**)&whiE, g_whi_e);
    cudaGetSymbolAddress((void**)&wloE, g_wlo_e);
    cudaGetSymbolAddress((void**)&whiD, g_whi_d);
    cudaGetSymbolAddress((void**)&wloD, g_wlo_d);

    pack_w_kernel<<<4096, 256>>>(encWhh, whiE, wloE);
    pack_w_kernel<<<4096, 256>>>(decWhh, whiD, wloD);
    zero_state_kernel<<<(B * H) / 256, 256>>>();

    lstm_persistent<<<dim3(32, 4), NTHREADS, SMEM_DYN>>>(
        inputs, whiE, wloE, whiD, wloD,
        encWih, encB, decWih, decB, linW, linB, out);
}

// round 16
// speedup vs baseline: 1.7465x; 1.7465x over previous
#include <cuda_runtime.h>
#include <cuda_bf16.h>
#include <stdint.h>
#include <math.h>

#define B      512
#define H      512
#define TENC   512
#define TDEC   128
#define TTOT   640
#define GROUP  32            // CTAs per mt barrier group
#define NMT    4
#define NTHREADS 512

#define ASTAGE_BYTES 40960   // hh 16KB + hl 16KB + wl 8KB per pair-stage
#define NASTAGE 4
#define WOFF   (NASTAGE * ASTAGE_BYTES)        // 163840
#define SMEM_DYN (WOFF + 8 * 8192 + 1024)      // 230400 <= 232448

// ---------------- persistent device state (no allocation allowed) ----------
static __device__ __align__(16) __nv_bfloat16 g_hhi0[B * H];
static __device__ __align__(16) __nv_bfloat16 g_hhi1[B * H];
static __device__ __align__(16) __nv_bfloat16 g_hlo0[B * H];
static __device__ __align__(16) __nv_bfloat16 g_hlo1[B * H];
static __device__ float g_xpart[GROUP * B];            // [nt][b] partial lin(h)
static __device__ __align__(16) __nv_bfloat16 g_whi_e[2048 * 512];
static __device__ __align__(16) __nv_bfloat16 g_wlo_e[2048 * 512];
static __device__ __align__(16) __nv_bfloat16 g_whi_d[2048 * 512];
static __device__ __align__(16) __nv_bfloat16 g_wlo_d[2048 * 512];
static __device__ unsigned g_cnt[NMT * 32];            // 128B-spaced counters
static __device__ volatile unsigned g_sense[NMT * 32];

// ---------------- helpers ----------------------------------------------------
__device__ __forceinline__ uint32_t smem_u32(const void* p) {
    uint32_t a;
    asm("{ .reg .u64 t; cvta.to.shared.u64 t, %1; cvt.u32.u64 %0, t; }"
        : "=r"(a) : "l"(p));
    return a;
}
__device__ __forceinline__ void cp16(uint32_t dst, const void* src) {
    asm volatile("cp.async.cg.shared.global [%0], [%1], 16;" :: "r"(dst), "l"(src));
}
__device__ __forceinline__ void cp_commit() {
    asm volatile("cp.async.commit_group;" ::: "memory");
}
__device__ __forceinline__ void cp_wait0() {
    asm volatile("cp.async.wait_group 0;" ::: "memory");
}
__device__ __forceinline__ void ldsm_x4(uint32_t& r0, uint32_t& r1,
                                        uint32_t& r2, uint32_t& r3, uint32_t addr) {
    asm volatile("ldmatrix.sync.aligned.m8n8.x4.shared.b16 {%0,%1,%2,%3}, [%4];"
                 : "=r"(r0), "=r"(r1), "=r"(r2), "=r"(r3) : "r"(addr));
}
__device__ __forceinline__ void mma_bf16(float* c, const uint32_t* a,
                                         uint32_t b0, uint32_t b1) {
    asm volatile(
        "mma.sync.aligned.m16n8k16.row.col.f32.bf16.bf16.f32 "
        "{%0,%1,%2,%3}, {%4,%5,%6,%7}, {%8,%9}, {%0,%1,%2,%3};"
        : "+f"(c[0]), "+f"(c[1]), "+f"(c[2]), "+f"(c[3])
        : "r"(a[0]), "r"(a[1]), "r"(a[2]), "r"(a[3]), "r"(b0), "r"(b1));
}
__device__ __forceinline__ float sigf(float x) { return 1.0f / (1.0f + __expf(-x)); }
__device__ __forceinline__ float tanhe(float x) {
    return __fmaf_rn(2.0f, sigf(2.0f * x), -1.0f);
}

// Sense-reversing barrier across the 32 CTAs of one mt group.
__device__ __forceinline__ void group_barrier(int mt, unsigned want) {
    __syncthreads();
    if (threadIdx.x == 0) {
        __threadfence();                       // release h / xpart writes
        if (atomicAdd(&g_cnt[mt * 32], 1u) == GROUP - 1u) {
            g_cnt[mt * 32] = 0u;
            __threadfence();
            g_sense[mt * 32] = want;
        } else {
            while (g_sense[mt * 32] != want) __nanosleep(32);
        }
        __threadfence();                       // acquire
    }
    __syncthreads();
}

// ---------------- prologue kernels -------------------------------------------
// Repack W (2048,512): packed row n' = nt*64 + g*16 + jl  <->  n = g*512 + nt*16 + jl
__global__ void pack_w_kernel(const float* __restrict__ W,
                              __nv_bfloat16* __restrict__ whi,
                              __nv_bfloat16* __restrict__ wlo) {
    int idx = blockIdx.x * 256 + threadIdx.x;
    int np = idx >> 9, k = idx & 511;
    int nt = np >> 6, r = np & 63;
    int n = (r >> 4) * 512 + nt * 16 + (r & 15);
    float w = W[n * 512 + k];
    __nv_bfloat16 hi = __float2bfloat16_rn(w);
    whi[idx] = hi;
    wlo[idx] = __float2bfloat16_rn(w - __bfloat162float(hi));
}

__global__ void zero_state_kernel() {
    int i = blockIdx.x * 256 + threadIdx.x;
    if (i < B * H) {
        g_hhi0[i] = __float2bfloat16(0.0f);
        g_hlo0[i] = __float2bfloat16(0.0f);
    }
}

// ---------------- the persistent encoder-decoder kernel ----------------------
__global__ void __launch_bounds__(NTHREADS, 1)
lstm_persistent(const float* __restrict__ inputs,
                const __nv_bfloat16* __restrict__ whiE, const __nv_bfloat16* __restrict__ wloE,
                const __nv_bfloat16* __restrict__ whiD, const __nv_bfloat16* __restrict__ wloD,
                const float* __restrict__ encWih, const float* __restrict__ encB,
                const float* __restrict__ decWih, const float* __restrict__ decB,
                const float* __restrict__ linW, const float* __restrict__ linb,
                float* __restrict__ out)
{
    extern __shared__ char dsmem[];
    uint32_t raw = smem_u32(dsmem);
    uint32_t sb  = (raw + 1023) & ~1023u;
    char* sp     = dsmem + (sb - raw);
    float* zs    = (float*)sp;     // 128 x 68 f32 (34 KB), reuses stages 0-1 post-drain

    const int tid  = threadIdx.x;
    const int wid  = tid >> 5;
    const int lane = tid & 31;
    const int wm   = wid >> 2;     // 0..3 : 32-row warp tile
    const int wn   = wid & 3;      // 0..3 : 16-col warp tile
    const int nt   = blockIdx.x;   // 0..31
    const int mt   = blockIdx.y;   // 0..3
    const int brow0 = mt * 128;

    // ---- staging map: thread covers 16B in 2 rows of a 128x64 chunk ---------
    const int gr  = tid >> 3;             // 0..63
    const int gce = (tid & 7) * 8;        // element col
    uint32_t soA[2];
#pragma unroll
    for (int i = 0; i < 2; i++) {
        int row = gr + 64 * i;
        soA[i] = (uint32_t)row * 128u + (((uint32_t)gce * 2) ^ (uint32_t)((row & 7) << 4));
    }

    // ---- ldmatrix addressing --------------------------------------------------
    const int lrow = lane & 15;
    const uint32_t kb2 = (uint32_t)((lane >> 4) * 16);
    uint32_t aoff[2], axor[2], boff, bxor;
#pragma unroll
    for (int mi = 0; mi < 2; mi++) {
        int r = wm * 32 + mi * 16 + lrow;
        aoff[mi] = (uint32_t)r * 128u;
        axor[mi] = (uint32_t)((r & 7) << 4);
    }
    {
        int r = wn * 16 + lrow;
        boff = (uint32_t)r * 128u;
        bxor = (uint32_t)((r & 7) << 4);
    }

    // ---- load W-hi tiles into resident smem (8 tiles x 8KB, kc 0..7) --------
    auto load_w = [&](const __nv_bfloat16* wh) {
#pragma unroll 4
        for (int j = 0; j < 8; ++j) {
            int slot = tid + j * NTHREADS;
            int tile = slot >> 9;             // 0..7 (k-chunk)
            int win  = slot & 511;
            int row  = win >> 3;
            int ce   = (win & 7) * 8;
            const __nv_bfloat16* src = wh
                + (size_t)(nt * 64 + row) * 512 + tile * 64 + ce;
            uint32_t dst = sb + WOFF + (uint32_t)tile * 8192u
                + (uint32_t)row * 128u
                + (((uint32_t)ce * 2u) ^ (uint32_t)((row & 7) << 4));
            cp16(dst, src);
        }
        cp_commit();
        cp_wait0();
        __syncthreads();
    };

    load_w(whiE);
    const __nv_bfloat16* wlcur = wloE;    // W-lo streamed per step
    const float* Wih  = encWih;
    const float* bias = encB;

    // ---- epilogue constants ----------------------------------------------------
    const int q    = tid & 3;
    const int eml  = tid >> 2;            // 0..127 (batch row in tile)
    const int jl0  = q * 4;
    const int jh0  = nt * 16 + jl0;
    const float lbv = __ldg(linb);
    const float4 lw = __ldg((const float4*)(linW + jh0));

    float creg[4];                        // cell state lives in registers
#pragma unroll
    for (int j = 0; j < 4; j++) creg[j] = 0.0f;

    for (int t = 0; t < TTOT; ++t) {
        if (t == TENC) {
            load_w(whiD);
            wlcur = wloD;
            Wih = decWih; bias = decB;
        }
        const __nv_bfloat16* hi = (t & 1) ? g_hhi1 : g_hhi0;
        const __nv_bfloat16* lo = (t & 1) ? g_hlo1 : g_hlo0;
        __nv_bfloat16* hio = (t & 1) ? g_hhi0 : g_hhi1;
        __nv_bfloat16* loo = (t & 1) ? g_hlo0 : g_hlo1;

        float acc[2][2][4];
#pragma unroll
        for (int mi = 0; mi < 2; mi++)
#pragma unroll
            for (int ni = 0; ni < 2; ni++)
#pragma unroll
                for (int qq = 0; qq < 4; qq++) acc[mi][ni][qq] = 0.0f;

        auto issue_pair = [&](int p) {
            const uint32_t ab = sb + (uint32_t)(p & 3) * ASTAGE_BYTES;
            const int koff = p * 64;
#pragma unroll
            for (int i = 0; i < 2; ++i) {
                const int row = gr + 64 * i;
                const size_t go = (size_t)(brow0 + row) * 512 + koff + gce;
                cp16(ab + soA[i],          hi + go);
                cp16(ab + 16384u + soA[i], lo + go);
            }
            // stream W-lo tile for this k-chunk (64 rows x 64 k = 8KB)
            cp16(ab + 32768u + soA[0],
                 wlcur + (size_t)(nt * 64 + gr) * 512 + koff + gce);
        };

        auto compute_pair = [&](int p) {
            const uint32_t ab  = sb + (uint32_t)(p & 3) * ASTAGE_BYTES;
            const uint32_t alb = ab + 16384u;
            const uint32_t whb = sb + WOFF + (uint32_t)p * 8192u;
            const uint32_t wlb = ab + 32768u;
#pragma unroll
            for (int s = 0; s < 4; ++s) {
                const uint32_t kb = (uint32_t)(s * 32);
                uint32_t ah[2][4], al[2][4];
#pragma unroll
                for (int mi = 0; mi < 2; ++mi) {
                    const uint32_t off = aoff[mi] + ((kb + kb2) ^ axor[mi]);
                    ldsm_x4(ah[mi][0], ah[mi][1], ah[mi][2], ah[mi][3], ab  + off);
                    ldsm_x4(al[mi][0], al[mi][1], al[mi][2], al[mi][3], alb + off);
                }
                uint32_t bh[2][2], bl[2][2];
                {
                    const uint32_t off = boff + ((kb + kb2) ^ bxor);
                    uint32_t q0, q1, q2, q3;
                    ldsm_x4(q0, q1, q2, q3, whb + off);
                    bh[0][0] = q0; bh[0][1] = q2;
                    bh[1][0] = q1; bh[1][1] = q3;
                    ldsm_x4(q0, q1, q2, q3, wlb + off);
                    bl[0][0] = q0; bl[0][1] = q2;
                    bl[1][0] = q1; bl[1][1] = q3;
                }
#pragma unroll
                for (int mi = 0; mi < 2; ++mi)
#pragma unroll
                    for (int ni = 0; ni < 2; ++ni) {
                        mma_bf16(acc[mi][ni], ah[mi], bh[ni][0], bh[ni][1]);
                        mma_bf16(acc[mi][ni], ah[mi], bl[ni][0], bl[ni][1]);
                        mma_bf16(acc[mi][ni], al[mi], bh[ni][0], bh[ni][1]);
                    }
            }
        };

        // pipeline: 4 rounds x 2 pairs, 4 stages, 1 wait+sync per round
        issue_pair(0); issue_pair(1); cp_commit();
        for (int i = 0; i < 4; ++i) {
            cp_wait0();          // pairs 2i, 2i+1 resident
            __syncthreads();     // visible to all; stages (2i+2)&3,(2i+3)&3 free
            if (i < 3) { issue_pair(2 * i + 2); issue_pair(2 * i + 3); cp_commit(); }
            compute_pair(2 * i);
            compute_pair(2 * i + 1);
        }
        __syncthreads();   // all compute done before zs overwrites stages 0-1

        // ---- accum -> zs (stride 68) -----------------------------------------
        {
            const int g  = lane >> 2;
            const int t2 = (lane & 3) * 2;
#pragma unroll
            for (int mi = 0; mi < 2; mi++)
#pragma unroll
                for (int ni = 0; ni < 2; ni++) {
                    const int row = wm * 32 + mi * 16 + g;
                    const int col = wn * 16 + ni * 8 + t2;
                    *(float2*)(zs + row * 68 + col) =
                        make_float2(acc[mi][ni][0], acc[mi][ni][1]);
                    *(float2*)(zs + (row + 8) * 68 + col) =
                        make_float2(acc[mi][ni][2], acc[mi][ni][3]);
                }
        }
        __syncthreads();

        // ---- gate pass: one row x 4 jh per thread -------------------------------
        {
            const int r = eml;
            const int b = brow0 + r;

            float xv;
            if (t < TENC) {
                xv = __ldg(inputs + (size_t)b * 512 + t);
            } else if (t == TENC) {
                xv = __ldg(inputs + (size_t)b * 512 + 511);
            } else {
                float s = 0.0f;
#pragma unroll
                for (int i = 0; i < 8; ++i)
                    s += g_xpart[(q * 8 + i) * B + b];
                s += __shfl_xor_sync(0xffffffffu, s, 1);
                s += __shfl_xor_sync(0xffffffffu, s, 2);
                xv = s + lbv;
                if (nt == 0 && q == 0)
                    out[(size_t)b * TDEC + (t - TENC - 1)] = xv;
            }

            const float4 wi0 = __ldg((const float4*)(Wih + jh0));
            const float4 wi1 = __ldg((const float4*)(Wih + 512 + jh0));
            const float4 wi2 = __ldg((const float4*)(Wih + 1024 + jh0));
            const float4 wi3 = __ldg((const float4*)(Wih + 1536 + jh0));
            const float4 bq0 = __ldg((const float4*)(bias + jh0));
            const float4 bq1 = __ldg((const float4*)(bias + 512 + jh0));
            const float4 bq2 = __ldg((const float4*)(bias + 1024 + jh0));
            const float4 bq3 = __ldg((const float4*)(bias + 1536 + jh0));

            float zi[4], zf[4], zg[4], zo[4];
            *(float4*)zi = *(const float4*)(zs + r * 68 +      jl0);
            *(float4*)zf = *(const float4*)(zs + r * 68 + 16 + jl0);
            *(float4*)zg = *(const float4*)(zs + r * 68 + 32 + jl0);
            *(float4*)zo = *(const float4*)(zs + r * 68 + 48 + jl0);

            const float* w0 = (const float*)&wi0; const float* b0p = (const float*)&bq0;
            const float* w1 = (const float*)&wi1; const float* b1p = (const float*)&bq1;
            const float* w2 = (const float*)&wi2; const float* b2p = (const float*)&bq2;
            const float* w3 = (const float*)&wi3; const float* b3p = (const float*)&bq3;

            float hv[4];
#pragma unroll
            for (int j = 0; j < 4; ++j) {
                const float vi = zi[j] + xv * w0[j] + b0p[j];
                const float vf = zf[j] + xv * w1[j] + b1p[j];
                const float vg = zg[j] + xv * w2[j] + b2p[j];
                const float vo = zo[j] + xv * w3[j] + b3p[j];
                const float cn = sigf(vf) * creg[j] + sigf(vi) * tanhe(vg);
                creg[j] = cn;
                hv[j] = sigf(vo) * tanhe(cn);
            }

            __nv_bfloat162 hh01 = __floats2bfloat162_rn(hv[0], hv[1]);
            __nv_bfloat162 hh23 = __floats2bfloat162_rn(hv[2], hv[3]);
            float l0 = hv[0] - __bfloat162float(__low2bfloat16(hh01));
            float l1 = hv[1] - __bfloat162float(__high2bfloat16(hh01));
            float l2 = hv[2] - __bfloat162float(__low2bfloat16(hh23));
            float l3 = hv[3] - __bfloat162float(__high2bfloat16(hh23));
            __nv_bfloat162 hl01 = __floats2bfloat162_rn(l0, l1);
            __nv_bfloat162 hl23 = __floats2bfloat162_rn(l2, l3);
            uint2 hp, lp;
            hp.x = *(uint32_t*)&hh01; hp.y = *(uint32_t*)&hh23;
            lp.x = *(uint32_t*)&hl01; lp.y = *(uint32_t*)&hl23;
            const size_t oidx = (size_t)b * H + jh0;
            *(uint2*)(hio + oidx) = hp;
            *(uint2*)(loo + oidx) = lp;

            if (t >= TENC) {   // partial lin(h_t) for the next step's x
                float s = hv[0] * lw.x + hv[1] * lw.y + hv[2] * lw.z + hv[3] * lw.w;
                s += __shfl_xor_sync(0xffffffffu, s, 1);
                s += __shfl_xor_sync(0xffffffffu, s, 2);
                if (q == 0) g_xpart[nt * B + b] = s;
            }
        }

        group_barrier(mt, (unsigned)((t + 1) & 1));
    }

    // ---- final output column: out[:, 127] = lin(h_final) -----------------------
    if (nt == 0 && tid < 128) {
        const int b = brow0 + tid;
        float s = lbv;
#pragma unroll
        for (int i = 0; i < 32; ++i) s += g_xpart[i * B + b];
        out[(size_t)b * TDEC + (TDEC - 1)] = s;
    }
}

// ---------------- launch ------------------------------------------------------
extern "C" void kernel_launch(void* const* d_in, const int* in_sizes, int n_in,
                              void* d_out, int out_size)
{
    (void)in_sizes; (void)n_in; (void)out_size;
    const float* inputs = (const float*)d_in[0];
    // d_in[1] = targets (unused: teacher_forcing_ratio == 0)
    const float* encWih = (const float*)d_in[2];
    const float* encWhh = (const float*)d_in[3];
    const float* encB   = (const float*)d_in[4];
    const float* decWih = (const float*)d_in[5];
    const float* decWhh = (const float*)d_in[6];
    const float* decB   = (const float*)d_in[7];
    const float* linW   = (const float*)d_in[8];
    const float* linB   = (const float*)d_in[9];
    float* out = (float*)d_out;

    cudaFuncSetAttribute(lstm_persistent,
                         cudaFuncAttributeMaxDynamicSharedMemorySize, SMEM_DYN);

    __nv_bfloat16 *whiE, *wloE, *whiD, *wloD;
    cudaGetSymbolAddress((void**)&whiE, g_whi_e);
    cudaGetSymbolAddress((void**)&wloE, g_wlo_e);
    cudaGetSymbolAddress((void**)&whiD, g_whi_d);
    cudaGetSymbolAddress((void**)&wloD, g_wlo_d);

    pack_w_kernel<<<4096, 256>>>(encWhh, whiE, wloE);
    pack_w_kernel<<<4096, 256>>>(decWhh, whiD, wloD);
    zero_state_kernel<<<(B * H) / 256, 256>>>();

    lstm_persistent<<<dim3(32, 4), NTHREADS, SMEM_DYN>>>(
        inputs, whiE, wloE, whiD, wloD,
        encWih, encB, decWih, decB, linW, linB, out);
}